// round 12
// baseline (speedup 1.0000x reference)
#include <cuda_runtime.h>
#include <stdint.h>

// Problem constants (fixed shapes per reference)
constexpr int D      = 256;    // IN_CHANNELS
constexpr int NPER   = 100;    // nodes per graph
constexpr int KSEL   = 50;     // ceil(0.5 * 100)
constexpr int NGRAPH = 1000;   // 100000 / 100

// out layout (float32, 150000 elems):
//   [0      , 50000)  node_index  (as float)
//   [50000  , 100000) cluster_index (= arange)
//   [100000 , 150000) weight (scores of selected nodes)

__global__ __launch_bounds__(256) void selectsparse_kernel(
    const float* __restrict__ x,
    const float* __restrict__ W,
    const float* __restrict__ b,
    float* __restrict__ out)
{
    __shared__ float s_scores[NPER];

    const int g    = blockIdx.x;
    const int tid  = threadIdx.x;
    const int lane = tid & 31;
    const int warp = tid >> 5;

    // Each lane holds its 8-float slice of W in registers (tiny, L2-hot).
    const float4 w0 = reinterpret_cast<const float4*>(W)[lane * 2 + 0];
    const float4 w1 = reinterpret_cast<const float4*>(W)[lane * 2 + 1];
    const float bias = b[0];

    // Accumulators start at bias; partials are atomically added below.
    if (tid < NPER) s_scores[tid] = bias;
    __syncthreads();

    const float4* xg = reinterpret_cast<const float4*>(x + (size_t)g * NPER * D);

    // Warp w handles node pair {2w, 2w+1}, then strides by 16 (proven pattern:
    // 4 independent LDG.128 per lane front-batched by ptxas).
    // Reduction: 2-level xor-fold (chain 52 cyc, was 130), then lanes 0-7 hold
    // disjoint 4-lane group sums -> fire-and-forget atomicAdd into smem. The
    // warp never waits on the reduction result.
    for (int n = warp * 2; n < NPER; n += 16) {
        const int n2 = n + 1;
        const float4* rowA = xg + n * (D / 4);
        float4 a0 = rowA[lane * 2 + 0];
        float4 a1 = rowA[lane * 2 + 1];
        float4 b0, b1;
        const bool has2 = (n2 < NPER);
        if (has2) {
            const float4* rowB = xg + n2 * (D / 4);
            b0 = rowB[lane * 2 + 0];
            b1 = rowB[lane * 2 + 1];
        }
        float sA = a0.x * w0.x + a0.y * w0.y + a0.z * w0.z + a0.w * w0.w
                 + a1.x * w1.x + a1.y * w1.y + a1.z * w1.z + a1.w * w1.w;
        float sB = 0.0f;
        if (has2) {
            sB = b0.x * w0.x + b0.y * w0.y + b0.z * w0.z + b0.w * w0.w
               + b1.x * w1.x + b1.y * w1.y + b1.z * w1.z + b1.w * w1.w;
        }
        sA += __shfl_xor_sync(0xffffffffu, sA, 16);
        sB += __shfl_xor_sync(0xffffffffu, sB, 16);
        sA += __shfl_xor_sync(0xffffffffu, sA, 8);
        sB += __shfl_xor_sync(0xffffffffu, sB, 8);
        // lanes 0-7: groups {l, l^8, l^16, l^24} are disjoint, cover all 32.
        if (lane < 8) {
            atomicAdd(&s_scores[n], sA);
            if (has2) atomicAdd(&s_scores[n2], sB);
        }
    }
    __syncthreads();   // drains pending smem atomics

    // Rank selection: rank(t) = #{j ordered before t} under descending score
    // with ascending-index tie-break -> unique rank in [0,100), identical
    // ordering to lax.top_k. rank < 50 -> emit at slot rank.
    if (tid < NPER) {
        const float st = s_scores[tid];
        int r = 0;
        #pragma unroll 4
        for (int j = 0; j < NPER; j++) {
            const float sj = s_scores[j];   // broadcast LDS, conflict-free
            r += (sj > st) | ((sj == st) & (j < tid));
        }
        if (r < KSEL) {
            const int node = g * NPER + tid;
            const int cl   = g * KSEL + r;
            out[cl]                     = (float)node;
            out[NGRAPH * KSEL + cl]     = (float)cl;
            out[2 * NGRAPH * KSEL + cl] = st;
        }
    }
}

extern "C" void kernel_launch(void* const* d_in, const int* in_sizes, int n_in,
                              void* d_out, int out_size) {
    // Identify inputs by element count (robust to metadata ordering):
    //   x: 25,600,000 f32 | batch: 100,000 (unused) | W: 256 | b: 1
    const float* x = nullptr;
    const float* W = nullptr;
    const float* b = nullptr;
    for (int i = 0; i < n_in; i++) {
        if      (in_sizes[i] == NGRAPH * NPER * D) x = (const float*)d_in[i];
        else if (in_sizes[i] == D)                 W = (const float*)d_in[i];
        else if (in_sizes[i] == 1)                 b = (const float*)d_in[i];
    }
    if (!x) x = (const float*)d_in[0];
    if (!W) W = (const float*)d_in[2];
    if (!b) b = (const float*)d_in[3];
    (void)out_size;
    selectsparse_kernel<<<NGRAPH, 256>>>(x, W, b, (float*)d_out);
}

// round 14
// speedup vs baseline: 1.3361x; 1.3361x over previous
#include <cuda_runtime.h>
#include <stdint.h>

// Problem constants (fixed shapes per reference)
constexpr int D      = 256;    // IN_CHANNELS
constexpr int NPER   = 100;    // nodes per graph
constexpr int KSEL   = 50;     // ceil(0.5 * 100)
constexpr int NGRAPH = 1000;   // 100000 / 100

// out layout (float32, 150000 elems):
//   [0      , 50000)  node_index  (as float)
//   [50000  , 100000) cluster_index (= arange)
//   [100000 , 150000) weight (scores of selected nodes)

__global__ __launch_bounds__(256) void selectsparse_kernel(
    const float* __restrict__ x,
    const float* __restrict__ W,
    const float* __restrict__ b,
    float* __restrict__ out)
{
    __shared__ float s_scores[NPER];

    const int g    = blockIdx.x;
    const int tid  = threadIdx.x;
    const int lane = tid & 31;
    const int warp = tid >> 5;

    // Each lane holds its 8-float slice of W in registers (tiny, L2-hot).
    const float4 w0 = reinterpret_cast<const float4*>(W)[lane * 2 + 0];
    const float4 w1 = reinterpret_cast<const float4*>(W)[lane * 2 + 1];
    const float bias = b[0];

    const float4* xg = reinterpret_cast<const float4*>(x + (size_t)g * NPER * D);

    // Warp w handles node pair {2w, 2w+1}, then strides by 16.
    // Pairs tile [0,16)+16t -> every node in [0,100) covered exactly once.
    // 4 independent LDG.128 per lane are issued before any consumption (MLP).
    for (int n = warp * 2; n < NPER; n += 16) {
        const int n2 = n + 1;
        const float4* rowA = xg + n * (D / 4);
        float4 a0 = rowA[lane * 2 + 0];
        float4 a1 = rowA[lane * 2 + 1];
        float4 b0, b1;
        const bool has2 = (n2 < NPER);
        if (has2) {
            const float4* rowB = xg + n2 * (D / 4);
            b0 = rowB[lane * 2 + 0];
            b1 = rowB[lane * 2 + 1];
        }
        float sA = a0.x * w0.x + a0.y * w0.y + a0.z * w0.z + a0.w * w0.w
                 + a1.x * w1.x + a1.y * w1.y + a1.z * w1.z + a1.w * w1.w;
        float sB = 0.0f;
        if (has2) {
            sB = b0.x * w0.x + b0.y * w0.y + b0.z * w0.z + b0.w * w0.w
               + b1.x * w1.x + b1.y * w1.y + b1.z * w1.z + b1.w * w1.w;
        }
        #pragma unroll
        for (int o = 16; o > 0; o >>= 1) {
            sA += __shfl_xor_sync(0xffffffffu, sA, o);
            sB += __shfl_xor_sync(0xffffffffu, sB, o);
        }
        if (lane == 0) {
            s_scores[n] = sA + bias;
            if (has2) s_scores[n2] = sB + bias;
        }
    }
    __syncthreads();   // the ONLY barrier

    // Rank selection: scores are distinct in practice, and the (j < t)
    // tie-break makes ranks unique regardless — identical ordering to
    // lax.top_k (descending, stable). Thread t owns node t; its rank is
    // the number of nodes ordered before it. rank < 50 -> emit at slot rank.
    if (tid < NPER) {
        const float st = s_scores[tid];
        int r = 0;
        #pragma unroll 4
        for (int j = 0; j < NPER; j++) {
            const float sj = s_scores[j];   // broadcast LDS, conflict-free
            r += (sj > st) | ((sj == st) & (j < tid));
        }
        if (r < KSEL) {
            const int node = g * NPER + tid;
            const int cl   = g * KSEL + r;
            out[cl]                     = (float)node;
            out[NGRAPH * KSEL + cl]     = (float)cl;
            out[2 * NGRAPH * KSEL + cl] = st;
        }
    }
}

extern "C" void kernel_launch(void* const* d_in, const int* in_sizes, int n_in,
                              void* d_out, int out_size) {
    // Identify inputs by element count (robust to metadata ordering):
    //   x: 25,600,000 f32 | batch: 100,000 (unused) | W: 256 | b: 1
    const float* x = nullptr;
    const float* W = nullptr;
    const float* b = nullptr;
    for (int i = 0; i < n_in; i++) {
        if      (in_sizes[i] == NGRAPH * NPER * D) x = (const float*)d_in[i];
        else if (in_sizes[i] == D)                 W = (const float*)d_in[i];
        else if (in_sizes[i] == 1)                 b = (const float*)d_in[i];
    }
    if (!x) x = (const float*)d_in[0];
    if (!W) W = (const float*)d_in[2];
    if (!b) b = (const float*)d_in[3];
    (void)out_size;
    selectsparse_kernel<<<NGRAPH, 256>>>(x, W, b, (float*)d_out);
}

// round 15
// speedup vs baseline: 1.4981x; 1.1212x over previous
#include <cuda_runtime.h>
#include <stdint.h>

// Problem constants (fixed shapes per reference)
constexpr int D      = 256;    // IN_CHANNELS
constexpr int NPER   = 100;    // nodes per graph
constexpr int KSEL   = 50;     // ceil(0.5 * 100)
constexpr int NGRAPH = 1000;   // 100000 / 100
constexpr int PSTRIDE = 33;    // 32 partials + 1 pad -> conflict-free column sums

// out layout (float32, 150000 elems):
//   [0      , 50000)  node_index  (as float)
//   [50000  , 100000) cluster_index (= arange)
//   [100000 , 150000) weight (scores of selected nodes)

__global__ __launch_bounds__(256) void selectsparse_kernel(
    const float* __restrict__ x,
    const float* __restrict__ W,
    const float* __restrict__ b,
    float* __restrict__ out)
{
    __shared__ float s_part[NPER * PSTRIDE];   // [node][lane] partial sums
    __shared__ float s_scores[NPER];

    const int g    = blockIdx.x;
    const int tid  = threadIdx.x;
    const int lane = tid & 31;
    const int warp = tid >> 5;

    // Each lane holds its 8-float slice of W in registers (tiny, L2-hot).
    const float4 w0 = reinterpret_cast<const float4*>(W)[lane * 2 + 0];
    const float4 w1 = reinterpret_cast<const float4*>(W)[lane * 2 + 1];
    const float bias = b[0];

    const float4* xg = reinterpret_cast<const float4*>(x + (size_t)g * NPER * D);

    // Warp w handles node pair {2w, 2w+1}, striding by 16 (proven pattern:
    // 4 independent LDG.128 per lane, front-batched by ptxas).
    // NO in-loop reduction: each lane fires its 8-elem partial into smem via
    // STS (issue-only, no result latency, distinct addresses). The warp goes
    // straight back to loading — zero shfl dead time.
    for (int n = warp * 2; n < NPER; n += 16) {
        const int n2 = n + 1;
        const float4* rowA = xg + n * (D / 4);
        const float4* rowB = rowA + (D / 4);   // n2 = n+1 always valid (100 even)
        float4 a0 = rowA[lane * 2 + 0];
        float4 a1 = rowA[lane * 2 + 1];
        float4 b0 = rowB[lane * 2 + 0];
        float4 b1 = rowB[lane * 2 + 1];
        float sA = a0.x * w0.x + a0.y * w0.y + a0.z * w0.z + a0.w * w0.w
                 + a1.x * w1.x + a1.y * w1.y + a1.z * w1.z + a1.w * w1.w;
        float sB = b0.x * w0.x + b0.y * w0.y + b0.z * w0.z + b0.w * w0.w
                 + b1.x * w1.x + b1.y * w1.y + b1.z * w1.z + b1.w * w1.w;
        s_part[n  * PSTRIDE + lane] = sA;
        s_part[n2 * PSTRIDE + lane] = sB;
    }
    __syncthreads();   // drains pending STS

    // Cross-lane sum moved here: thread t sums its node's 32 partials.
    // Stride-33 rows -> lanes read distinct banks at every step (conflict-free).
    if (tid < NPER) {
        const float* p = &s_part[tid * PSTRIDE];
        float s = bias;
        #pragma unroll
        for (int j = 0; j < 32; j += 4) {   // 4-way ILP over independent LDS
            s += p[j] + p[j + 1] + p[j + 2] + p[j + 3];
        }
        s_scores[tid] = s;
    }
    __syncthreads();

    // Rank selection: rank(t) = #{j ordered before t} under descending score
    // with ascending-index tie-break -> unique rank in [0,100), identical
    // ordering to lax.top_k. rank < 50 -> emit at slot rank.
    if (tid < NPER) {
        const float st = s_scores[tid];
        int r = 0;
        #pragma unroll 4
        for (int j = 0; j < NPER; j++) {
            const float sj = s_scores[j];   // broadcast LDS, conflict-free
            r += (sj > st) | ((sj == st) & (j < tid));
        }
        if (r < KSEL) {
            const int node = g * NPER + tid;
            const int cl   = g * KSEL + r;
            out[cl]                     = (float)node;
            out[NGRAPH * KSEL + cl]     = (float)cl;
            out[2 * NGRAPH * KSEL + cl] = st;
        }
    }
}

extern "C" void kernel_launch(void* const* d_in, const int* in_sizes, int n_in,
                              void* d_out, int out_size) {
    // Identify inputs by element count (robust to metadata ordering):
    //   x: 25,600,000 f32 | batch: 100,000 (unused) | W: 256 | b: 1
    const float* x = nullptr;
    const float* W = nullptr;
    const float* b = nullptr;
    for (int i = 0; i < n_in; i++) {
        if      (in_sizes[i] == NGRAPH * NPER * D) x = (const float*)d_in[i];
        else if (in_sizes[i] == D)                 W = (const float*)d_in[i];
        else if (in_sizes[i] == 1)                 b = (const float*)d_in[i];
    }
    if (!x) x = (const float*)d_in[0];
    if (!W) W = (const float*)d_in[2];
    if (!b) b = (const float*)d_in[3];
    (void)out_size;
    selectsparse_kernel<<<NGRAPH, 256>>>(x, W, b, (float*)d_out);
}